// round 2
// baseline (speedup 1.0000x reference)
#include <cuda_runtime.h>
#include <cstddef>

#define NUSERS 200000
#define NITEMS 100000
#define DIM    64
#define NEDGES 3200000

// -------- scratch (no allocations allowed; __device__ globals are the sanctioned path) ----
__device__ __align__(256) float g_hu[(size_t)NUSERS * DIM];  // layer-0 user output
__device__ __align__(256) float g_hi[(size_t)NITEMS * DIM];  // layer-0 item output
__device__ __align__(256) float g_nu[(size_t)NUSERS * DIM];  // neigh_u accumulator
__device__ __align__(256) float g_ni[(size_t)NITEMS * DIM];  // neigh_i accumulator

// ---------------------------------------------------------------------------
// Zero a float4 buffer
// ---------------------------------------------------------------------------
__global__ void zero_kernel(float4* __restrict__ p, int n4) {
    int i = blockIdx.x * blockDim.x + threadIdx.x;
    if (i < n4) p[i] = make_float4(0.f, 0.f, 0.f, 0.f);
}

// ---------------------------------------------------------------------------
// SpMM scatter: out[dst[e]] += w[e] * h[src[e]]
// 16 threads per edge, float4 per thread, vector red.global (sm_90+)
// ---------------------------------------------------------------------------
__global__ void __launch_bounds__(256) spmm_kernel(
    const float* __restrict__ h,
    const int*   __restrict__ dst,
    const int*   __restrict__ src,
    const float* __restrict__ w,
    float*       __restrict__ out)
{
    unsigned gt = blockIdx.x * blockDim.x + threadIdx.x;
    unsigned e  = gt >> 4;
    unsigned c  = (gt & 15u) << 2;          // float offset within the 64-float row
    if (e >= NEDGES) return;

    int   s  = __ldg(src + e);
    int   d  = __ldg(dst + e);
    float wv = __ldg(w + e);

    float4 v = *reinterpret_cast<const float4*>(h + (size_t)s * DIM + c);
    float* p = out + (size_t)d * DIM + c;
    asm volatile("red.global.add.v4.f32 [%0], {%1,%2,%3,%4};"
                 :: "l"(p), "f"(v.x * wv), "f"(v.y * wv), "f"(v.z * wv), "f"(v.w * wv)
                 : "memory");
}

// ---------------------------------------------------------------------------
// Fused: y = relu(concat(h,neigh) @ W^T); out = y / max(||y||_2, 1e-12)
// W is [64][128] row-major. One warp per output row; 8 warps / block.
// Wt in shared with XOR swizzle -> conflict-free transpose store AND read.
// ---------------------------------------------------------------------------
__global__ void __launch_bounds__(256) dense_norm_kernel(
    const float* __restrict__ h,
    const float* __restrict__ neigh,
    const float* __restrict__ W,
    float*       __restrict__ out,
    int nrows)
{
    __shared__ float sWt[128][64];   // sWt[k][ swz(j,k) ] = W[j][k]
    __shared__ float sx[8][128];

    int t    = threadIdx.x;
    int lane = t & 31;
    int wp   = t >> 5;

    // Cooperative transpose load of W: coalesced LDG, swizzled STS (conflict-free)
    #pragma unroll
    for (int i = 0; i < 32; i++) {
        int idx = t + i * 256;            // 0..8191
        int j = idx >> 7;                 // 0..63
        int k = idx & 127;                // 0..127
        int col = (j & 32) | ((j ^ k) & 31);
        sWt[k][col] = __ldg(W + j * 128 + k);
    }

    int row = blockIdx.x * 8 + wp;
    bool valid = (row < nrows);
    if (valid) {
        const float* hr = h     + (size_t)row * DIM;
        const float* nr = neigh + (size_t)row * DIM;
        sx[wp][lane]      = hr[lane];
        sx[wp][lane + 32] = hr[lane + 32];
        sx[wp][64 + lane]      = nr[lane];
        sx[wp][64 + lane + 32] = nr[lane + 32];
    }
    __syncthreads();
    if (!valid) return;

    float acc0 = 0.f, acc1 = 0.f;
    #pragma unroll 8
    for (int k = 0; k < 128; k++) {
        float xk = sx[wp][k];
        int c0 = lane ^ (k & 31);
        acc0 = fmaf(xk, sWt[k][c0],      acc0);
        acc1 = fmaf(xk, sWt[k][c0 + 32], acc1);
    }

    float v0 = fmaxf(acc0, 0.f);
    float v1 = fmaxf(acc1, 0.f);
    float ss = v0 * v0 + v1 * v1;
    #pragma unroll
    for (int o = 16; o; o >>= 1) ss += __shfl_xor_sync(0xffffffffu, ss, o);
    float nrm = sqrtf(ss);
    float s   = 1.0f / fmaxf(nrm, 1e-12f);

    out[(size_t)row * DIM + lane]      = v0 * s;
    out[(size_t)row * DIM + lane + 32] = v1 * s;
}

// ---------------------------------------------------------------------------
extern "C" void kernel_launch(void* const* d_in, const int* in_sizes, int n_in,
                              void* d_out, int out_size)
{
    const float* user_emb = (const float*)d_in[0];
    const float* item_emb = (const float*)d_in[1];
    const float* Wu       = (const float*)d_in[2];   // [2][64][128]
    const float* Wi       = (const float*)d_in[3];
    const int*   u_idx    = (const int*)  d_in[4];
    const int*   i_idx    = (const int*)  d_in[5];
    const float* w_u2i    = (const float*)d_in[6];
    const float* w_i2u    = (const float*)d_in[7];

    float* out_u = (float*)d_out;
    float* out_i = out_u + (size_t)NUSERS * DIM;

    float *hu, *hi, *nu, *ni;
    cudaGetSymbolAddress((void**)&hu, g_hu);
    cudaGetSymbolAddress((void**)&hi, g_hi);
    cudaGetSymbolAddress((void**)&nu, g_nu);
    cudaGetSymbolAddress((void**)&ni, g_ni);

    const int ZT = 256;
    const int n4u = NUSERS * DIM / 4;   // 3.2M
    const int n4i = NITEMS * DIM / 4;   // 1.6M
    const int spmm_blocks  = (NEDGES * 16) / 256;        // 200000
    const int dense_u_blks = (NUSERS + 7) / 8;           // 25000
    const int dense_i_blks = (NITEMS + 7) / 8;           // 12500

    // ---------------- Layer 0 (inputs come straight from d_in) ----------------
    zero_kernel<<<(n4u + ZT - 1) / ZT, ZT>>>((float4*)nu, n4u);
    zero_kernel<<<(n4i + ZT - 1) / ZT, ZT>>>((float4*)ni, n4i);

    // neigh_u[u] += w_u2i[e] * h_i[i_idx[e]]
    spmm_kernel<<<spmm_blocks, 256>>>(item_emb, u_idx, i_idx, w_u2i, nu);
    // neigh_i[i] += w_i2u[e] * h_u[u_idx[e]]
    spmm_kernel<<<spmm_blocks, 256>>>(user_emb, i_idx, u_idx, w_i2u, ni);

    dense_norm_kernel<<<dense_u_blks, 256>>>(user_emb, nu, Wu,        hu, NUSERS);
    dense_norm_kernel<<<dense_i_blks, 256>>>(item_emb, ni, Wi,        hi, NITEMS);

    // ---------------- Layer 1 (writes straight into d_out) ----------------
    zero_kernel<<<(n4u + ZT - 1) / ZT, ZT>>>((float4*)nu, n4u);
    zero_kernel<<<(n4i + ZT - 1) / ZT, ZT>>>((float4*)ni, n4i);

    spmm_kernel<<<spmm_blocks, 256>>>(hi, u_idx, i_idx, w_u2i, nu);
    spmm_kernel<<<spmm_blocks, 256>>>(hu, i_idx, u_idx, w_i2u, ni);

    dense_norm_kernel<<<dense_u_blks, 256>>>(hu, nu, Wu + 64 * 128, out_u, NUSERS);
    dense_norm_kernel<<<dense_i_blks, 256>>>(hi, ni, Wi + 64 * 128, out_i, NITEMS);
}

// round 4
// speedup vs baseline: 1.1804x; 1.1804x over previous
#include <cuda_runtime.h>
#include <cstddef>

#define NUSERS 200000
#define NITEMS 100000
#define DIM    64
#define NEDGES 3200000

// -------- scratch (no allocations allowed; __device__ globals are the sanctioned path) ----
__device__ __align__(256) float g_hu[(size_t)NUSERS * DIM];  // layer-0 user output
__device__ __align__(256) float g_hi[(size_t)NITEMS * DIM];  // layer-0 item output
__device__ __align__(256) float g_nu[(size_t)NUSERS * DIM];  // neigh_u accumulator
__device__ __align__(256) float g_ni[(size_t)NITEMS * DIM];  // neigh_i accumulator

// ---------------------------------------------------------------------------
// SpMM scatter: out[dst[e]] += w[e] * h[src[e]]
// 16 threads per edge, float4 per thread, vector red.global (sm_90+)
// ---------------------------------------------------------------------------
__global__ void __launch_bounds__(256) spmm_kernel(
    const float* __restrict__ h,
    const int*   __restrict__ dst,
    const int*   __restrict__ src,
    const float* __restrict__ w,
    float*       __restrict__ out)
{
    unsigned gt = blockIdx.x * blockDim.x + threadIdx.x;
    unsigned e  = gt >> 4;
    unsigned c  = (gt & 15u) << 2;          // float offset within the 64-float row
    if (e >= NEDGES) return;

    int   s  = __ldg(src + e);
    int   d  = __ldg(dst + e);
    float wv = __ldg(w + e);

    float4 v = *reinterpret_cast<const float4*>(h + (size_t)s * DIM + c);
    float* p = out + (size_t)d * DIM + c;
    asm volatile("red.global.add.v4.f32 [%0], {%1,%2,%3,%4};"
                 :: "l"(p), "f"(v.x * wv), "f"(v.y * wv), "f"(v.z * wv), "f"(v.w * wv)
                 : "memory");
}

// ---------------------------------------------------------------------------
// Register-tiled fused dense+relu+L2norm:
//   y = relu(concat(h,neigh) @ W^T);  out = y / max(||y||_2, 1e-12)
// Block tile: 128 rows x 64 cols, K=128 (whole reduction), 256 threads.
// Thread tile: 4 rows x 8 cols -> 32 FMA per k vs 6 LDS slots per k.
// smem: sX[128][132] (row-major x), sW[128][68] (transposed W). ~100 KB dyn.
// ---------------------------------------------------------------------------
#define SX_STRIDE 132
#define SW_STRIDE 68
#define DN_SMEM ((128 * SX_STRIDE + 128 * SW_STRIDE) * 4)

__global__ void __launch_bounds__(256) dense_norm_tiled(
    const float* __restrict__ h,
    const float* __restrict__ neigh,
    const float* __restrict__ W,
    float*       __restrict__ out,
    int nrows)
{
    extern __shared__ float smem[];
    float* sX = smem;                    // [128][SX_STRIDE]
    float* sW = smem + 128 * SX_STRIDE;  // [128][SW_STRIDE]

    const int t   = threadIdx.x;
    const int tx  = t & 7;       // col group: cols tx*8 .. tx*8+7
    const int ty  = t >> 3;      // row group: rows ty*4 .. ty*4+3
    const int row0 = blockIdx.x * 128;

    // ---- load X tile: 128 rows x 128 k (first 64 from h, last 64 from neigh)
    #pragma unroll
    for (int i = 0; i < 16; i++) {
        int idx = t + i * 256;            // 0..4095
        int m   = idx >> 5;               // 0..127
        int kq  = idx & 31;               // float4 index; k = 4*kq
        int row = row0 + m;
        float4 v = make_float4(0.f, 0.f, 0.f, 0.f);
        if (row < nrows) {
            const float* sp = (kq < 16)
                ? (h     + (size_t)row * DIM + 4 * kq)
                : (neigh + (size_t)row * DIM + 4 * (kq - 16));
            v = *reinterpret_cast<const float4*>(sp);
        }
        *reinterpret_cast<float4*>(sX + m * SX_STRIDE + 4 * kq) = v;
    }

    // ---- load W transposed: sW[k][j] = W[j][k]
    #pragma unroll
    for (int i = 0; i < 8; i++) {
        int idx = t + i * 256;            // 0..2047
        int j   = idx >> 5;               // 0..63
        int kq  = idx & 31;
        float4 v = *reinterpret_cast<const float4*>(W + j * 128 + 4 * kq);
        sW[(4 * kq + 0) * SW_STRIDE + j] = v.x;
        sW[(4 * kq + 1) * SW_STRIDE + j] = v.y;
        sW[(4 * kq + 2) * SW_STRIDE + j] = v.z;
        sW[(4 * kq + 3) * SW_STRIDE + j] = v.w;
    }
    __syncthreads();

    float acc[4][8];
    #pragma unroll
    for (int i = 0; i < 4; i++)
        #pragma unroll
        for (int j = 0; j < 8; j++) acc[i][j] = 0.f;

    const float* xb = sX + (ty * 4) * SX_STRIDE;
    const float* wb = sW + tx * 8;

    #pragma unroll 8
    for (int k = 0; k < 128; k++) {
        float4 w0 = *reinterpret_cast<const float4*>(wb + k * SW_STRIDE);
        float4 w1 = *reinterpret_cast<const float4*>(wb + k * SW_STRIDE + 4);
        float x0 = xb[0 * SX_STRIDE + k];
        float x1 = xb[1 * SX_STRIDE + k];
        float x2 = xb[2 * SX_STRIDE + k];
        float x3 = xb[3 * SX_STRIDE + k];
        #pragma unroll
        for (int i = 0; i < 4; i++) {
            float xi = (i == 0) ? x0 : (i == 1) ? x1 : (i == 2) ? x2 : x3;
            acc[i][0] = fmaf(xi, w0.x, acc[i][0]);
            acc[i][1] = fmaf(xi, w0.y, acc[i][1]);
            acc[i][2] = fmaf(xi, w0.z, acc[i][2]);
            acc[i][3] = fmaf(xi, w0.w, acc[i][3]);
            acc[i][4] = fmaf(xi, w1.x, acc[i][4]);
            acc[i][5] = fmaf(xi, w1.y, acc[i][5]);
            acc[i][6] = fmaf(xi, w1.z, acc[i][6]);
            acc[i][7] = fmaf(xi, w1.w, acc[i][7]);
        }
    }

    // ---- relu + row L2 norm (reduce over the 8-thread octet that owns a row)
    #pragma unroll
    for (int i = 0; i < 4; i++) {
        float ss = 0.f;
        #pragma unroll
        for (int j = 0; j < 8; j++) {
            float v = fmaxf(acc[i][j], 0.f);
            acc[i][j] = v;
            ss = fmaf(v, v, ss);
        }
        ss += __shfl_xor_sync(0xffffffffu, ss, 1);
        ss += __shfl_xor_sync(0xffffffffu, ss, 2);
        ss += __shfl_xor_sync(0xffffffffu, ss, 4);
        float s = 1.0f / fmaxf(sqrtf(ss), 1e-12f);

        int row = row0 + ty * 4 + i;
        if (row < nrows) {
            float4 o0 = make_float4(acc[i][0] * s, acc[i][1] * s, acc[i][2] * s, acc[i][3] * s);
            float4 o1 = make_float4(acc[i][4] * s, acc[i][5] * s, acc[i][6] * s, acc[i][7] * s);
            float* op = out + (size_t)row * DIM + tx * 8;
            *reinterpret_cast<float4*>(op)     = o0;
            *reinterpret_cast<float4*>(op + 4) = o1;
        }
    }
}

// ---------------------------------------------------------------------------
extern "C" void kernel_launch(void* const* d_in, const int* in_sizes, int n_in,
                              void* d_out, int out_size)
{
    const float* user_emb = (const float*)d_in[0];
    const float* item_emb = (const float*)d_in[1];
    const float* Wu       = (const float*)d_in[2];   // [2][64][128]
    const float* Wi       = (const float*)d_in[3];
    const int*   u_idx    = (const int*)  d_in[4];
    const int*   i_idx    = (const int*)  d_in[5];
    const float* w_u2i    = (const float*)d_in[6];
    const float* w_i2u    = (const float*)d_in[7];

    float* out_u = (float*)d_out;
    float* out_i = out_u + (size_t)NUSERS * DIM;

    float *hu, *hi, *nu, *ni;
    cudaGetSymbolAddress((void**)&hu, g_hu);
    cudaGetSymbolAddress((void**)&hi, g_hi);
    cudaGetSymbolAddress((void**)&nu, g_nu);
    cudaGetSymbolAddress((void**)&ni, g_ni);

    static bool attr_set = false;
    if (!attr_set) {
        cudaFuncSetAttribute(dense_norm_tiled,
                             cudaFuncAttributeMaxDynamicSharedMemorySize, DN_SMEM);
        attr_set = true;
    }

    const size_t bu = (size_t)NUSERS * DIM * sizeof(float);
    const size_t bi = (size_t)NITEMS * DIM * sizeof(float);
    const int spmm_blocks  = (NEDGES * 16) / 256;          // 200000
    const int dense_u_blks = (NUSERS + 127) / 128;         // 1563
    const int dense_i_blks = (NITEMS + 127) / 128;         // 782

    // ---------------- Layer 0 (inputs come straight from d_in) ----------------
    cudaMemsetAsync(nu, 0, bu);
    cudaMemsetAsync(ni, 0, bi);

    spmm_kernel<<<spmm_blocks, 256>>>(item_emb, u_idx, i_idx, w_u2i, nu);
    spmm_kernel<<<spmm_blocks, 256>>>(user_emb, i_idx, u_idx, w_i2u, ni);

    dense_norm_tiled<<<dense_u_blks, 256, DN_SMEM>>>(user_emb, nu, Wu, hu, NUSERS);
    dense_norm_tiled<<<dense_i_blks, 256, DN_SMEM>>>(item_emb, ni, Wi, hi, NITEMS);

    // ---------------- Layer 1 (writes straight into d_out) ----------------
    cudaMemsetAsync(nu, 0, bu);
    cudaMemsetAsync(ni, 0, bi);

    spmm_kernel<<<spmm_blocks, 256>>>(hi, u_idx, i_idx, w_u2i, nu);
    spmm_kernel<<<spmm_blocks, 256>>>(hu, i_idx, u_idx, w_i2u, ni);

    dense_norm_tiled<<<dense_u_blks, 256, DN_SMEM>>>(hu, nu, Wu + 64 * 128, out_u, NUSERS);
    dense_norm_tiled<<<dense_i_blks, 256, DN_SMEM>>>(hi, ni, Wi + 64 * 128, out_i, NITEMS);
}

// round 5
// speedup vs baseline: 1.4368x; 1.2172x over previous
#include <cuda_runtime.h>
#include <cstddef>

#define NUSERS 200000
#define NITEMS 100000
#define DIM    64
#define NEDGES 3200000

// -------- scratch (no allocations allowed; __device__ globals are the sanctioned path) ----
__device__ __align__(256) float g_hu[(size_t)NUSERS * DIM];  // layer-0 user output
__device__ __align__(256) float g_hi[(size_t)NITEMS * DIM];  // layer-0 item output
__device__ __align__(256) float g_nu[(size_t)NUSERS * DIM];  // neigh_u accumulator
__device__ __align__(256) float g_ni[(size_t)NITEMS * DIM];  // neigh_i accumulator

// ---------------------------------------------------------------------------
// SpMM scatter: out[dst[e]] += w[e] * h[src[e]]
// 16 threads per edge, float4 per thread, vector red.global (sm_90+)
// ---------------------------------------------------------------------------
__global__ void __launch_bounds__(256) spmm_kernel(
    const float* __restrict__ h,
    const int*   __restrict__ dst,
    const int*   __restrict__ src,
    const float* __restrict__ w,
    float*       __restrict__ out)
{
    unsigned gt = blockIdx.x * blockDim.x + threadIdx.x;
    unsigned e  = gt >> 4;
    unsigned c  = (gt & 15u) << 2;          // float offset within the 64-float row
    if (e >= NEDGES) return;

    int   s  = __ldg(src + e);
    int   d  = __ldg(dst + e);
    float wv = __ldg(w + e);

    float4 v = *reinterpret_cast<const float4*>(h + (size_t)s * DIM + c);
    float* p = out + (size_t)d * DIM + c;
    asm volatile("red.global.add.v4.f32 [%0], {%1,%2,%3,%4};"
                 :: "l"(p), "f"(v.x * wv), "f"(v.y * wv), "f"(v.z * wv), "f"(v.w * wv)
                 : "memory");
}

// ---------------------------------------------------------------------------
// Register-tiled fused dense+relu+L2norm, K split in 2 chunks of 64:
//   chunk 0 streams h, chunk 1 streams neigh (concat falls out of the split).
// Block tile: 128 rows x 64 cols, 256 threads, thread tile 4x8.
// smem: sX[128][68] + sW[64][68] = 52.2 KB -> 4 blocks/SM (50% occ).
// ---------------------------------------------------------------------------
#define SX_STRIDE 68
#define SW_STRIDE 68
#define DN_SMEM ((128 * SX_STRIDE + 64 * SW_STRIDE) * 4)

__global__ void __launch_bounds__(256, 4) dense_norm_tiled(
    const float* __restrict__ h,
    const float* __restrict__ neigh,
    const float* __restrict__ W,     // [64][128] row-major
    float*       __restrict__ out,
    int nrows)
{
    extern __shared__ float smem[];
    float* sX = smem;                    // [128][SX_STRIDE]
    float* sW = smem + 128 * SX_STRIDE;  // [64][SW_STRIDE]  (transposed chunk of W)

    const int t    = threadIdx.x;
    const int tx   = t & 7;       // col group: cols tx*8 .. tx*8+7
    const int ty   = t >> 3;      // row group: rows ty*4 .. ty*4+3
    const int row0 = blockIdx.x * 128;

    float acc[4][8];
    #pragma unroll
    for (int i = 0; i < 4; i++)
        #pragma unroll
        for (int j = 0; j < 8; j++) acc[i][j] = 0.f;

    #pragma unroll
    for (int c = 0; c < 2; c++) {
        const float* xsrc = (c == 0) ? h : neigh;

        if (c) __syncthreads();   // protect smem reuse between chunks

        // ---- load X chunk: 128 rows x 64 k (float4, coalesced)
        #pragma unroll
        for (int i = 0; i < 8; i++) {
            int idx = t + i * 256;            // 0..2047
            int m   = idx >> 4;               // 0..127
            int kq  = idx & 15;               // float4 index within chunk
            int row = row0 + m;
            float4 v = make_float4(0.f, 0.f, 0.f, 0.f);
            if (row < nrows)
                v = *reinterpret_cast<const float4*>(xsrc + (size_t)row * DIM + 4 * kq);
            *reinterpret_cast<float4*>(sX + m * SX_STRIDE + 4 * kq) = v;
        }

        // ---- load W chunk transposed: sW[kk][j] = W[j][c*64 + kk]
        #pragma unroll
        for (int i = 0; i < 4; i++) {
            int idx = t + i * 256;            // 0..1023
            int j   = idx >> 4;               // 0..63
            int kq  = idx & 15;
            float4 v = *reinterpret_cast<const float4*>(W + j * 128 + c * 64 + 4 * kq);
            sW[(4 * kq + 0) * SW_STRIDE + j] = v.x;
            sW[(4 * kq + 1) * SW_STRIDE + j] = v.y;
            sW[(4 * kq + 2) * SW_STRIDE + j] = v.z;
            sW[(4 * kq + 3) * SW_STRIDE + j] = v.w;
        }
        __syncthreads();

        const float* xb = sX + (ty * 4) * SX_STRIDE;
        const float* wb = sW + tx * 8;

        #pragma unroll 8
        for (int k = 0; k < 64; k++) {
            float4 w0 = *reinterpret_cast<const float4*>(wb + k * SW_STRIDE);
            float4 w1 = *reinterpret_cast<const float4*>(wb + k * SW_STRIDE + 4);
            float x0 = xb[0 * SX_STRIDE + k];
            float x1 = xb[1 * SX_STRIDE + k];
            float x2 = xb[2 * SX_STRIDE + k];
            float x3 = xb[3 * SX_STRIDE + k];
            #pragma unroll
            for (int i = 0; i < 4; i++) {
                float xi = (i == 0) ? x0 : (i == 1) ? x1 : (i == 2) ? x2 : x3;
                acc[i][0] = fmaf(xi, w0.x, acc[i][0]);
                acc[i][1] = fmaf(xi, w0.y, acc[i][1]);
                acc[i][2] = fmaf(xi, w0.z, acc[i][2]);
                acc[i][3] = fmaf(xi, w0.w, acc[i][3]);
                acc[i][4] = fmaf(xi, w1.x, acc[i][4]);
                acc[i][5] = fmaf(xi, w1.y, acc[i][5]);
                acc[i][6] = fmaf(xi, w1.z, acc[i][6]);
                acc[i][7] = fmaf(xi, w1.w, acc[i][7]);
            }
        }
    }

    // ---- relu + row L2 norm (reduce over the 8-thread octet that owns a row)
    #pragma unroll
    for (int i = 0; i < 4; i++) {
        float ss = 0.f;
        #pragma unroll
        for (int j = 0; j < 8; j++) {
            float v = fmaxf(acc[i][j], 0.f);
            acc[i][j] = v;
            ss = fmaf(v, v, ss);
        }
        ss += __shfl_xor_sync(0xffffffffu, ss, 1);
        ss += __shfl_xor_sync(0xffffffffu, ss, 2);
        ss += __shfl_xor_sync(0xffffffffu, ss, 4);
        float s = 1.0f / fmaxf(sqrtf(ss), 1e-12f);

        int row = row0 + ty * 4 + i;
        if (row < nrows) {
            float4 o0 = make_float4(acc[i][0] * s, acc[i][1] * s, acc[i][2] * s, acc[i][3] * s);
            float4 o1 = make_float4(acc[i][4] * s, acc[i][5] * s, acc[i][6] * s, acc[i][7] * s);
            float* op = out + (size_t)row * DIM + tx * 8;
            *reinterpret_cast<float4*>(op)     = o0;
            *reinterpret_cast<float4*>(op + 4) = o1;
        }
    }
}

// ---------------------------------------------------------------------------
extern "C" void kernel_launch(void* const* d_in, const int* in_sizes, int n_in,
                              void* d_out, int out_size)
{
    const float* user_emb = (const float*)d_in[0];
    const float* item_emb = (const float*)d_in[1];
    const float* Wu       = (const float*)d_in[2];   // [2][64][128]
    const float* Wi       = (const float*)d_in[3];
    const int*   u_idx    = (const int*)  d_in[4];
    const int*   i_idx    = (const int*)  d_in[5];
    const float* w_u2i    = (const float*)d_in[6];
    const float* w_i2u    = (const float*)d_in[7];

    float* out_u = (float*)d_out;
    float* out_i = out_u + (size_t)NUSERS * DIM;

    float *hu, *hi, *nu, *ni;
    cudaGetSymbolAddress((void**)&hu, g_hu);
    cudaGetSymbolAddress((void**)&hi, g_hi);
    cudaGetSymbolAddress((void**)&nu, g_nu);
    cudaGetSymbolAddress((void**)&ni, g_ni);

    // One-time infra (first call is the uncaptured correctness run)
    static cudaStream_t s1 = nullptr;
    static cudaEvent_t evFork = nullptr, evHU = nullptr, evHI = nullptr, evEnd = nullptr;
    if (!s1) {
        cudaFuncSetAttribute(dense_norm_tiled,
                             cudaFuncAttributeMaxDynamicSharedMemorySize, DN_SMEM);
        cudaStreamCreateWithFlags(&s1, cudaStreamNonBlocking);
        cudaEventCreateWithFlags(&evFork, cudaEventDisableTiming);
        cudaEventCreateWithFlags(&evHU,   cudaEventDisableTiming);
        cudaEventCreateWithFlags(&evHI,   cudaEventDisableTiming);
        cudaEventCreateWithFlags(&evEnd,  cudaEventDisableTiming);
    }

    const size_t bu = (size_t)NUSERS * DIM * sizeof(float);
    const size_t bi = (size_t)NITEMS * DIM * sizeof(float);
    const int spmm_blocks  = (NEDGES * 16) / 256;          // 200000
    const int dense_u_blks = (NUSERS + 127) / 128;         // 1563
    const int dense_i_blks = (NITEMS + 127) / 128;         // 782

    cudaStream_t s0 = 0;  // launch stream (same one the harness captures)

    // fork
    cudaEventRecord(evFork, s0);
    cudaStreamWaitEvent(s1, evFork, 0);

    // ---------------- Layer 0 ----------------
    // user chain on s0: nu = A_u2i @ item_emb ; hu = dense(user_emb, nu, Wu0)
    cudaMemsetAsync(nu, 0, bu, s0);
    spmm_kernel<<<spmm_blocks, 256, 0, s0>>>(item_emb, u_idx, i_idx, w_u2i, nu);
    dense_norm_tiled<<<dense_u_blks, 256, DN_SMEM, s0>>>(user_emb, nu, Wu, hu, NUSERS);
    cudaEventRecord(evHU, s0);

    // item chain on s1: ni = A_i2u @ user_emb ; hi = dense(item_emb, ni, Wi0)
    cudaMemsetAsync(ni, 0, bi, s1);
    spmm_kernel<<<spmm_blocks, 256, 0, s1>>>(user_emb, i_idx, u_idx, w_i2u, ni);
    dense_norm_tiled<<<dense_i_blks, 256, DN_SMEM, s1>>>(item_emb, ni, Wi, hi, NITEMS);
    cudaEventRecord(evHI, s1);

    // ---------------- Layer 1 ----------------
    // user chain on s0 needs hi (from s1)
    cudaStreamWaitEvent(s0, evHI, 0);
    cudaMemsetAsync(nu, 0, bu, s0);
    spmm_kernel<<<spmm_blocks, 256, 0, s0>>>(hi, u_idx, i_idx, w_u2i, nu);
    dense_norm_tiled<<<dense_u_blks, 256, DN_SMEM, s0>>>(hu, nu, Wu + 64 * 128, out_u, NUSERS);

    // item chain on s1 needs hu (from s0)
    cudaStreamWaitEvent(s1, evHU, 0);
    cudaMemsetAsync(ni, 0, bi, s1);
    spmm_kernel<<<spmm_blocks, 256, 0, s1>>>(hu, i_idx, u_idx, w_i2u, ni);
    dense_norm_tiled<<<dense_i_blks, 256, DN_SMEM, s1>>>(hi, ni, Wi + 64 * 128, out_i, NITEMS);

    // join
    cudaEventRecord(evEnd, s1);
    cudaStreamWaitEvent(s0, evEnd, 0);
}

// round 9
// speedup vs baseline: 2.1765x; 1.5148x over previous
#include <cuda_runtime.h>
#include <cstddef>

#define NUSERS 200000
#define NITEMS 100000
#define DIM    64
#define NEDGES 3200000

// -------- scratch (no allocations allowed; __device__ globals are the sanctioned path) ----
__device__ __align__(256) float g_hu[(size_t)NUSERS * DIM];
__device__ __align__(256) float g_hi[(size_t)NITEMS * DIM];
__device__ __align__(256) float g_nu[(size_t)NUSERS * DIM];
__device__ __align__(256) float g_ni[(size_t)NITEMS * DIM];

// CSR scratch (rebuilt every call; no caching)
__device__ int  g_cnt_u[NUSERS];
__device__ int  g_rp_u[NUSERS + 1];
__device__ int  g_pos_u[NUSERS];
__device__ int2 g_edge_u[NEDGES];      // {src_item, w_bits}
__device__ int  g_cnt_i[NITEMS];
__device__ int  g_rp_i[NITEMS + 1];
__device__ int  g_pos_i[NITEMS];
__device__ int2 g_edge_i[NEDGES];      // {src_user, w_bits}
__device__ int  g_bsum_u[256];
__device__ int  g_bsum_i[256];

// ---------------------------------------------------------------------------
// CSR build: histogram -> 3-kernel exclusive scan -> edge scatter
// ---------------------------------------------------------------------------
__global__ void hist_kernel(const int* __restrict__ idx, int* __restrict__ cnt, int n) {
    int e = blockIdx.x * blockDim.x + threadIdx.x;
    if (e < n) atomicAdd(cnt + idx[e], 1);
}

__global__ void scan_blocksum(const int* __restrict__ cnt, int* __restrict__ bsum, int n) {
    __shared__ int sh[1024];
    int i = blockIdx.x * 1024 + threadIdx.x;
    int v = (i < n) ? cnt[i] : 0;
    sh[threadIdx.x] = v;
    __syncthreads();
    for (int o = 512; o > 0; o >>= 1) {
        if (threadIdx.x < o) sh[threadIdx.x] += sh[threadIdx.x + o];
        __syncthreads();
    }
    if (threadIdx.x == 0) bsum[blockIdx.x] = sh[0];
}

__global__ void scan_bsums(int* __restrict__ bsum, int nb) {   // single block, 256 thr
    __shared__ int sh[256];
    int t = threadIdx.x;
    int v = (t < nb) ? bsum[t] : 0;
    sh[t] = v;
    __syncthreads();
    for (int o = 1; o < 256; o <<= 1) {
        int x = (t >= o) ? sh[t - o] : 0;
        __syncthreads();
        sh[t] += x;
        __syncthreads();
    }
    if (t < nb) bsum[t] = sh[t] - v;   // exclusive
}

__global__ void scan_write(const int* __restrict__ cnt, const int* __restrict__ bsum,
                           int* __restrict__ rowptr, int* __restrict__ pos, int n) {
    __shared__ int sh[1024];
    int t = threadIdx.x;
    int i = blockIdx.x * 1024 + t;
    int v = (i < n) ? cnt[i] : 0;
    sh[t] = v;
    __syncthreads();
    for (int o = 1; o < 1024; o <<= 1) {
        int x = (t >= o) ? sh[t - o] : 0;
        __syncthreads();
        sh[t] += x;
        __syncthreads();
    }
    if (i < n) {
        int start = bsum[blockIdx.x] + sh[t] - v;
        rowptr[i] = start;
        pos[i]    = start;
    }
    if (i == 0) rowptr[n] = NEDGES;
}

__global__ void scatter_edges(const int* __restrict__ dst, const int* __restrict__ src,
                              const float* __restrict__ w, int* __restrict__ pos,
                              int2* __restrict__ edges, int n) {
    int e = blockIdx.x * blockDim.x + threadIdx.x;
    if (e >= n) return;
    int p = atomicAdd(pos + dst[e], 1);
    edges[p] = make_int2(src[e], __float_as_int(w[e]));
}

// ---------------------------------------------------------------------------
// Gather SpMM: out[r] = sum_{j in row r} w_j * h[src_j]   (warp per row)
// ---------------------------------------------------------------------------
__global__ void __launch_bounds__(256) spmm_gather(
    const float* __restrict__ h,
    const int*   __restrict__ rowptr,
    const int2*  __restrict__ edges,
    float*       __restrict__ out,
    int nrows)
{
    int warp = (blockIdx.x * 256 + threadIdx.x) >> 5;
    int lane = threadIdx.x & 31;
    if (warp >= nrows) return;

    int start = __ldg(rowptr + warp);
    int end   = __ldg(rowptr + warp + 1);

    float2 acc = make_float2(0.f, 0.f);
    int j = start;
    for (; j + 1 < end; j += 2) {
        int2 e0 = __ldg(edges + j);
        int2 e1 = __ldg(edges + j + 1);
        float2 v0 = *reinterpret_cast<const float2*>(h + (size_t)e0.x * DIM + 2 * lane);
        float2 v1 = *reinterpret_cast<const float2*>(h + (size_t)e1.x * DIM + 2 * lane);
        float w0 = __int_as_float(e0.y);
        float w1 = __int_as_float(e1.y);
        acc.x = fmaf(w0, v0.x, acc.x);
        acc.y = fmaf(w0, v0.y, acc.y);
        acc.x = fmaf(w1, v1.x, acc.x);
        acc.y = fmaf(w1, v1.y, acc.y);
    }
    if (j < end) {
        int2 e0 = __ldg(edges + j);
        float2 v0 = *reinterpret_cast<const float2*>(h + (size_t)e0.x * DIM + 2 * lane);
        float w0 = __int_as_float(e0.y);
        acc.x = fmaf(w0, v0.x, acc.x);
        acc.y = fmaf(w0, v0.y, acc.y);
    }
    *reinterpret_cast<float2*>(out + (size_t)warp * DIM + 2 * lane) = acc;
}

// ---------------------------------------------------------------------------
// Register-tiled fused dense+relu+L2norm (unchanged from R4)
// ---------------------------------------------------------------------------
#define SX_STRIDE 68
#define SW_STRIDE 68
#define DN_SMEM ((128 * SX_STRIDE + 64 * SW_STRIDE) * 4)

__global__ void __launch_bounds__(256, 4) dense_norm_tiled(
    const float* __restrict__ h,
    const float* __restrict__ neigh,
    const float* __restrict__ W,     // [64][128] row-major
    float*       __restrict__ out,
    int nrows)
{
    extern __shared__ float smem[];
    float* sX = smem;                    // [128][SX_STRIDE]
    float* sW = smem + 128 * SX_STRIDE;  // [64][SW_STRIDE]

    const int t    = threadIdx.x;
    const int tx   = t & 7;
    const int ty   = t >> 3;
    const int row0 = blockIdx.x * 128;

    float acc[4][8];
    #pragma unroll
    for (int i = 0; i < 4; i++)
        #pragma unroll
        for (int j = 0; j < 8; j++) acc[i][j] = 0.f;

    #pragma unroll
    for (int c = 0; c < 2; c++) {
        const float* xsrc = (c == 0) ? h : neigh;
        if (c) __syncthreads();

        #pragma unroll
        for (int i = 0; i < 8; i++) {
            int idx = t + i * 256;
            int m   = idx >> 4;
            int kq  = idx & 15;
            int row = row0 + m;
            float4 v = make_float4(0.f, 0.f, 0.f, 0.f);
            if (row < nrows)
                v = *reinterpret_cast<const float4*>(xsrc + (size_t)row * DIM + 4 * kq);
            *reinterpret_cast<float4*>(sX + m * SX_STRIDE + 4 * kq) = v;
        }
        #pragma unroll
        for (int i = 0; i < 4; i++) {
            int idx = t + i * 256;
            int j   = idx >> 4;
            int kq  = idx & 15;
            float4 v = *reinterpret_cast<const float4*>(W + j * 128 + c * 64 + 4 * kq);
            sW[(4 * kq + 0) * SW_STRIDE + j] = v.x;
            sW[(4 * kq + 1) * SW_STRIDE + j] = v.y;
            sW[(4 * kq + 2) * SW_STRIDE + j] = v.z;
            sW[(4 * kq + 3) * SW_STRIDE + j] = v.w;
        }
        __syncthreads();

        const float* xb = sX + (ty * 4) * SX_STRIDE;
        const float* wb = sW + tx * 8;

        #pragma unroll 8
        for (int k = 0; k < 64; k++) {
            float4 w0 = *reinterpret_cast<const float4*>(wb + k * SW_STRIDE);
            float4 w1 = *reinterpret_cast<const float4*>(wb + k * SW_STRIDE + 4);
            float x0 = xb[0 * SX_STRIDE + k];
            float x1 = xb[1 * SX_STRIDE + k];
            float x2 = xb[2 * SX_STRIDE + k];
            float x3 = xb[3 * SX_STRIDE + k];
            #pragma unroll
            for (int i = 0; i < 4; i++) {
                float xi = (i == 0) ? x0 : (i == 1) ? x1 : (i == 2) ? x2 : x3;
                acc[i][0] = fmaf(xi, w0.x, acc[i][0]);
                acc[i][1] = fmaf(xi, w0.y, acc[i][1]);
                acc[i][2] = fmaf(xi, w0.z, acc[i][2]);
                acc[i][3] = fmaf(xi, w0.w, acc[i][3]);
                acc[i][4] = fmaf(xi, w1.x, acc[i][4]);
                acc[i][5] = fmaf(xi, w1.y, acc[i][5]);
                acc[i][6] = fmaf(xi, w1.z, acc[i][6]);
                acc[i][7] = fmaf(xi, w1.w, acc[i][7]);
            }
        }
    }

    #pragma unroll
    for (int i = 0; i < 4; i++) {
        float ss = 0.f;
        #pragma unroll
        for (int j = 0; j < 8; j++) {
            float v = fmaxf(acc[i][j], 0.f);
            acc[i][j] = v;
            ss = fmaf(v, v, ss);
        }
        ss += __shfl_xor_sync(0xffffffffu, ss, 1);
        ss += __shfl_xor_sync(0xffffffffu, ss, 2);
        ss += __shfl_xor_sync(0xffffffffu, ss, 4);
        float s = 1.0f / fmaxf(sqrtf(ss), 1e-12f);

        int row = row0 + ty * 4 + i;
        if (row < nrows) {
            float4 o0 = make_float4(acc[i][0] * s, acc[i][1] * s, acc[i][2] * s, acc[i][3] * s);
            float4 o1 = make_float4(acc[i][4] * s, acc[i][5] * s, acc[i][6] * s, acc[i][7] * s);
            float* op = out + (size_t)row * DIM + tx * 8;
            *reinterpret_cast<float4*>(op)     = o0;
            *reinterpret_cast<float4*>(op + 4) = o1;
        }
    }
}

// ---------------------------------------------------------------------------
static void build_csr(cudaStream_t s, const int* dst, const int* src, const float* w,
                      int* cnt, int* bsum, int* rowptr, int* pos, int2* edges, int nrows)
{
    cudaMemsetAsync(cnt, 0, nrows * sizeof(int), s);
    hist_kernel<<<(NEDGES + 255) / 256, 256, 0, s>>>(dst, cnt, NEDGES);
    int nb = (nrows + 1023) / 1024;
    scan_blocksum<<<nb, 1024, 0, s>>>(cnt, bsum, nrows);
    scan_bsums<<<1, 256, 0, s>>>(bsum, nb);
    scan_write<<<nb, 1024, 0, s>>>(cnt, bsum, rowptr, pos, nrows);
    scatter_edges<<<(NEDGES + 255) / 256, 256, 0, s>>>(dst, src, w, pos, edges, NEDGES);
}

extern "C" void kernel_launch(void* const* d_in, const int* in_sizes, int n_in,
                              void* d_out, int out_size)
{
    const float* user_emb = (const float*)d_in[0];
    const float* item_emb = (const float*)d_in[1];
    const float* Wu       = (const float*)d_in[2];   // [2][64][128]
    const float* Wi       = (const float*)d_in[3];
    const int*   u_idx    = (const int*)  d_in[4];
    const int*   i_idx    = (const int*)  d_in[5];
    const float* w_u2i    = (const float*)d_in[6];
    const float* w_i2u    = (const float*)d_in[7];

    float* out_u = (float*)d_out;
    float* out_i = out_u + (size_t)NUSERS * DIM;

    float *hu, *hi, *nu, *ni;
    int *cnt_u, *rp_u, *pos_u, *cnt_i, *rp_i, *pos_i, *bsum_u, *bsum_i;
    int2 *edge_u, *edge_i;
    cudaGetSymbolAddress((void**)&hu, g_hu);
    cudaGetSymbolAddress((void**)&hi, g_hi);
    cudaGetSymbolAddress((void**)&nu, g_nu);
    cudaGetSymbolAddress((void**)&ni, g_ni);
    cudaGetSymbolAddress((void**)&cnt_u, g_cnt_u);
    cudaGetSymbolAddress((void**)&rp_u,  g_rp_u);
    cudaGetSymbolAddress((void**)&pos_u, g_pos_u);
    cudaGetSymbolAddress((void**)&edge_u, g_edge_u);
    cudaGetSymbolAddress((void**)&cnt_i, g_cnt_i);
    cudaGetSymbolAddress((void**)&rp_i,  g_rp_i);
    cudaGetSymbolAddress((void**)&pos_i, g_pos_i);
    cudaGetSymbolAddress((void**)&edge_i, g_edge_i);
    cudaGetSymbolAddress((void**)&bsum_u, g_bsum_u);
    cudaGetSymbolAddress((void**)&bsum_i, g_bsum_i);

    static cudaStream_t s1 = nullptr;
    static cudaEvent_t evFork = nullptr, evHU = nullptr, evHI = nullptr, evEnd = nullptr;
    if (!s1) {
        cudaFuncSetAttribute(dense_norm_tiled,
                             cudaFuncAttributeMaxDynamicSharedMemorySize, DN_SMEM);
        cudaStreamCreateWithFlags(&s1, cudaStreamNonBlocking);
        cudaEventCreateWithFlags(&evFork, cudaEventDisableTiming);
        cudaEventCreateWithFlags(&evHU,   cudaEventDisableTiming);
        cudaEventCreateWithFlags(&evHI,   cudaEventDisableTiming);
        cudaEventCreateWithFlags(&evEnd,  cudaEventDisableTiming);
    }

    const int gather_u_blks = (NUSERS * 32 + 255) / 256;   // warp per row
    const int gather_i_blks = (NITEMS * 32 + 255) / 256;
    const int dense_u_blks  = (NUSERS + 127) / 128;
    const int dense_i_blks  = (NITEMS + 127) / 128;

    cudaStream_t s0 = 0;

    cudaEventRecord(evFork, s0);
    cudaStreamWaitEvent(s1, evFork, 0);

    // ---- CSR builds (independent; one per stream) ----
    build_csr(s0, u_idx, i_idx, w_u2i, cnt_u, bsum_u, rp_u, pos_u, edge_u, NUSERS);
    build_csr(s1, i_idx, u_idx, w_i2u, cnt_i, bsum_i, rp_i, pos_i, edge_i, NITEMS);

    // ---------------- Layer 0 ----------------
    spmm_gather<<<gather_u_blks, 256, 0, s0>>>(item_emb, rp_u, edge_u, nu, NUSERS);
    dense_norm_tiled<<<dense_u_blks, 256, DN_SMEM, s0>>>(user_emb, nu, Wu, hu, NUSERS);
    cudaEventRecord(evHU, s0);

    spmm_gather<<<gather_i_blks, 256, 0, s1>>>(user_emb, rp_i, edge_i, ni, NITEMS);
    dense_norm_tiled<<<dense_i_blks, 256, DN_SMEM, s1>>>(item_emb, ni, Wi, hi, NITEMS);
    cudaEventRecord(evHI, s1);

    // ---------------- Layer 1 ----------------
    cudaStreamWaitEvent(s0, evHI, 0);
    spmm_gather<<<gather_u_blks, 256, 0, s0>>>(hi, rp_u, edge_u, nu, NUSERS);
    dense_norm_tiled<<<dense_u_blks, 256, DN_SMEM, s0>>>(hu, nu, Wu + 64 * 128, out_u, NUSERS);

    cudaStreamWaitEvent(s1, evHU, 0);
    spmm_gather<<<gather_i_blks, 256, 0, s1>>>(hu, rp_i, edge_i, ni, NITEMS);
    dense_norm_tiled<<<dense_i_blks, 256, DN_SMEM, s1>>>(hi, ni, Wi + 64 * 128, out_i, NITEMS);

    cudaEventRecord(evEnd, s1);
    cudaStreamWaitEvent(s0, evEnd, 0);
}